// round 2
// baseline (speedup 1.0000x reference)
#include <cuda_runtime.h>
#include <math.h>

#define NTOK 8192
#define DIM 1024
#define TRIPLE 3072
#define TSEQ 2048
#define NB 4
#define NH 16
#define DH 64
#define ATT_SCALE 0.125f

// Scratch (allocation-free: device globals)
__device__ float g_xn[(size_t)NTOK * DIM];     // 32 MB
__device__ float g_qkv[(size_t)NTOK * TRIPLE]; // 96 MB
__device__ float g_ao[(size_t)NTOK * DIM];     // 32 MB

// ---------------------------------------------------------------------------
// LayerNorm: one block per row of 1024, 256 threads x float4
// ---------------------------------------------------------------------------
__global__ __launch_bounds__(256) void ln_kernel(
    const float* __restrict__ x,
    const float* __restrict__ gamma,
    const float* __restrict__ beta)
{
    int row = blockIdx.x;
    int t = threadIdx.x;
    const float4* xr = reinterpret_cast<const float4*>(x) + (size_t)row * (DIM / 4);
    float4 v = xr[t];

    __shared__ float red[8];

    float s = v.x + v.y + v.z + v.w;
    #pragma unroll
    for (int o = 16; o > 0; o >>= 1) s += __shfl_xor_sync(0xffffffffu, s, o);
    if ((t & 31) == 0) red[t >> 5] = s;
    __syncthreads();
    float mu = 0.f;
    #pragma unroll
    for (int i = 0; i < 8; i++) mu += red[i];
    mu *= (1.0f / DIM);
    __syncthreads();

    float dx = v.x - mu, dy = v.y - mu, dz = v.z - mu, dw = v.w - mu;
    float s2 = dx * dx + dy * dy + dz * dz + dw * dw;
    #pragma unroll
    for (int o = 16; o > 0; o >>= 1) s2 += __shfl_xor_sync(0xffffffffu, s2, o);
    if ((t & 31) == 0) red[t >> 5] = s2;
    __syncthreads();
    float var = 0.f;
    #pragma unroll
    for (int i = 0; i < 8; i++) var += red[i];
    var *= (1.0f / DIM);
    float r = rsqrtf(var + 1e-5f);

    float4 g = reinterpret_cast<const float4*>(gamma)[t];
    float4 bb = reinterpret_cast<const float4*>(beta)[t];
    float4 o;
    o.x = dx * r * g.x + bb.x;
    o.y = dy * r * g.y + bb.y;
    o.z = dz * r * g.z + bb.z;
    o.w = dw * r * g.w + bb.w;
    reinterpret_cast<float4*>(g_xn)[(size_t)row * (DIM / 4) + t] = o;
}

// ---------------------------------------------------------------------------
// SGEMM: C[M,N] = A[M,K] @ B[K,N] (+bias). 128x128x32 tiles, 256 thr, 8x8/thr
// M % 128 == 0, N % 128 == 0, K % 32 == 0
// ---------------------------------------------------------------------------
template <bool HAS_BIAS>
__global__ __launch_bounds__(256) void sgemm_kernel(
    const float* __restrict__ A,
    const float* __restrict__ Bm,
    float* __restrict__ C,
    int M, int N, int K,
    const float* __restrict__ bias)
{
    const int BK = 32;
    __shared__ __align__(16) float As[128][36]; // natural [m][k], pad to 36
    __shared__ __align__(16) float Bs[BK][128]; // natural [k][n]

    int t = threadIdx.x;
    int tx = t & 15;        // n-direction (8 cols each)
    int ty = t >> 4;        // m-direction (8 rows each)
    int mBase = blockIdx.y * 128;
    int nBase = blockIdx.x * 128;

    float acc[8][8];
    #pragma unroll
    for (int i = 0; i < 8; i++)
        #pragma unroll
        for (int j = 0; j < 8; j++) acc[i][j] = 0.f;

    for (int k0 = 0; k0 < K; k0 += BK) {
        // Load A tile: 128 x 32 floats = 1024 float4; 4 per thread, coalesced.
        #pragma unroll
        for (int i = 0; i < 4; i++) {
            int fid = t + i * 256;
            int ar = fid >> 3;
            int ak = (fid & 7) << 2;
            float4 v = *reinterpret_cast<const float4*>(
                &A[(size_t)(mBase + ar) * K + k0 + ak]);
            *reinterpret_cast<float4*>(&As[ar][ak]) = v;
        }
        // Load B tile: 32 x 128 floats = 1024 float4; coalesced, natural.
        #pragma unroll
        for (int i = 0; i < 4; i++) {
            int fid = t + i * 256;
            int br = fid >> 5;
            int bc = (fid & 31) << 2;
            float4 v = *reinterpret_cast<const float4*>(
                &Bm[(size_t)(k0 + br) * N + nBase + bc]);
            *reinterpret_cast<float4*>(&Bs[br][bc]) = v;
        }
        __syncthreads();

        #pragma unroll 8
        for (int k = 0; k < BK; k++) {
            float a[8], b[8];
            #pragma unroll
            for (int i = 0; i < 8; i++) a[i] = As[ty * 8 + i][k];
            float4 b0 = *reinterpret_cast<const float4*>(&Bs[k][tx * 8]);
            float4 b1 = *reinterpret_cast<const float4*>(&Bs[k][tx * 8 + 4]);
            b[0] = b0.x; b[1] = b0.y; b[2] = b0.z; b[3] = b0.w;
            b[4] = b1.x; b[5] = b1.y; b[6] = b1.z; b[7] = b1.w;
            #pragma unroll
            for (int i = 0; i < 8; i++)
                #pragma unroll
                for (int j = 0; j < 8; j++)
                    acc[i][j] = fmaf(a[i], b[j], acc[i][j]);
        }
        __syncthreads();
    }

    // Write back (two float4 per row)
    #pragma unroll
    for (int i = 0; i < 8; i++) {
        int row = mBase + ty * 8 + i;
        int col = nBase + tx * 8;
        float4 c0, c1;
        c0.x = acc[i][0]; c0.y = acc[i][1]; c0.z = acc[i][2]; c0.w = acc[i][3];
        c1.x = acc[i][4]; c1.y = acc[i][5]; c1.z = acc[i][6]; c1.w = acc[i][7];
        if (HAS_BIAS) {
            c0.x += bias[col + 0]; c0.y += bias[col + 1];
            c0.z += bias[col + 2]; c0.w += bias[col + 3];
            c1.x += bias[col + 4]; c1.y += bias[col + 5];
            c1.z += bias[col + 6]; c1.w += bias[col + 7];
        }
        *reinterpret_cast<float4*>(&C[(size_t)row * N + col]) = c0;
        *reinterpret_cast<float4*>(&C[(size_t)row * N + col + 4]) = c1;
    }
}

// ---------------------------------------------------------------------------
// Flash attention, fp32. One block = (batch b, head h, 64-query tile).
// 256 threads as 16x16; each thread owns 4 q-rows x 4 cols microtiles.
// smem: Qs[64][65], KPs[64][65] (K tile, then reused for P), Vs[64][65]
// ---------------------------------------------------------------------------
#define ATT_STRIDE 65
#define ATT_SMEM_FLOATS (3 * 64 * ATT_STRIDE)

__global__ __launch_bounds__(256) void attn_kernel(
    const float* __restrict__ qkv,
    float* __restrict__ ao)
{
    extern __shared__ float sm[];
    float* Qs  = sm;                       // [64][65] natural [q][d], pre-scaled
    float* KPs = sm + 64 * ATT_STRIDE;     // [64][65] K natural [k][d]; later P [q][k]
    float* Vs  = sm + 2 * 64 * ATT_STRIDE; // [64][65] natural [k][d]

    int t = threadIdx.x;
    int tx = t & 15;   // 4 cols (k for S, d for O)
    int ty = t >> 4;   // 4 q rows
    int qtile = blockIdx.x;
    int h = blockIdx.y;
    int b = blockIdx.z;

    size_t tokRowBase = (size_t)b * TSEQ;
    const float* Qg = qkv + tokRowBase * TRIPLE + h * DH;
    const float* Kg = qkv + tokRowBase * TRIPLE + DIM + h * DH;
    const float* Vg = qkv + tokRowBase * TRIPLE + 2 * DIM + h * DH;
    int qBase = qtile * 64;

    // Load Q tile (scaled). 64 rows x 64 cols = 1024 float4, coalesced.
    #pragma unroll
    for (int i = 0; i < 4; i++) {
        int fid = t + i * 256;
        int r = fid >> 4;
        int c4 = (fid & 15) << 2;
        float4 v = *reinterpret_cast<const float4*>(
            &Qg[(size_t)(qBase + r) * TRIPLE + c4]);
        Qs[r * ATT_STRIDE + c4 + 0] = v.x * ATT_SCALE;
        Qs[r * ATT_STRIDE + c4 + 1] = v.y * ATT_SCALE;
        Qs[r * ATT_STRIDE + c4 + 2] = v.z * ATT_SCALE;
        Qs[r * ATT_STRIDE + c4 + 3] = v.w * ATT_SCALE;
    }

    float m_i[4], l_i[4], acc[4][4];
    #pragma unroll
    for (int i = 0; i < 4; i++) {
        m_i[i] = -INFINITY;
        l_i[i] = 0.f;
        #pragma unroll
        for (int j = 0; j < 4; j++) acc[i][j] = 0.f;
    }

    for (int kt = 0; kt < TSEQ / 64; kt++) {
        int kBase = kt * 64;
        // Load K and V tiles (coalesced reads; scalar smem stores)
        #pragma unroll
        for (int i = 0; i < 4; i++) {
            int fid = t + i * 256;
            int r = fid >> 4;
            int c4 = (fid & 15) << 2;
            float4 kv = *reinterpret_cast<const float4*>(
                &Kg[(size_t)(kBase + r) * TRIPLE + c4]);
            KPs[r * ATT_STRIDE + c4 + 0] = kv.x;
            KPs[r * ATT_STRIDE + c4 + 1] = kv.y;
            KPs[r * ATT_STRIDE + c4 + 2] = kv.z;
            KPs[r * ATT_STRIDE + c4 + 3] = kv.w;
            float4 vv = *reinterpret_cast<const float4*>(
                &Vg[(size_t)(kBase + r) * TRIPLE + c4]);
            Vs[r * ATT_STRIDE + c4 + 0] = vv.x;
            Vs[r * ATT_STRIDE + c4 + 1] = vv.y;
            Vs[r * ATT_STRIDE + c4 + 2] = vv.z;
            Vs[r * ATT_STRIDE + c4 + 3] = vv.w;
        }
        __syncthreads();

        // S = Q K^T (64x64), thread microtile 4q x 4k
        float s[4][4];
        #pragma unroll
        for (int i = 0; i < 4; i++)
            #pragma unroll
            for (int j = 0; j < 4; j++) s[i][j] = 0.f;
        #pragma unroll 4
        for (int d = 0; d < DH; d++) {
            float a[4], bb[4];
            #pragma unroll
            for (int i = 0; i < 4; i++) a[i] = Qs[(ty * 4 + i) * ATT_STRIDE + d];
            #pragma unroll
            for (int j = 0; j < 4; j++) bb[j] = KPs[(tx * 4 + j) * ATT_STRIDE + d];
            #pragma unroll
            for (int i = 0; i < 4; i++)
                #pragma unroll
                for (int j = 0; j < 4; j++)
                    s[i][j] = fmaf(a[i], bb[j], s[i][j]);
        }
        __syncthreads();  // everyone done reading K tile before P overwrites it

        // Online softmax update (16 tx lanes share each q row; xor-reduce)
        #pragma unroll
        for (int i = 0; i < 4; i++) {
            float rm = s[i][0];
            rm = fmaxf(rm, s[i][1]);
            rm = fmaxf(rm, s[i][2]);
            rm = fmaxf(rm, s[i][3]);
            #pragma unroll
            for (int o = 8; o > 0; o >>= 1)
                rm = fmaxf(rm, __shfl_xor_sync(0xffffffffu, rm, o));
            float mnew = fmaxf(m_i[i], rm);
            float alpha = __expf(m_i[i] - mnew);
            float rs = 0.f;
            #pragma unroll
            for (int j = 0; j < 4; j++) {
                float p = __expf(s[i][j] - mnew);
                s[i][j] = p;
                rs += p;
            }
            #pragma unroll
            for (int o = 8; o > 0; o >>= 1)
                rs += __shfl_xor_sync(0xffffffffu, rs, o);
            l_i[i] = l_i[i] * alpha + rs;
            m_i[i] = mnew;
            #pragma unroll
            for (int j = 0; j < 4; j++) acc[i][j] *= alpha;
        }

        // Write P into KPs as [q][k]
        #pragma unroll
        for (int i = 0; i < 4; i++)
            #pragma unroll
            for (int j = 0; j < 4; j++)
                KPs[(ty * 4 + i) * ATT_STRIDE + tx * 4 + j] = s[i][j];
        __syncthreads();

        // O += P @ V, thread microtile 4q x 4d (d cols = tx*4..)
        #pragma unroll 4
        for (int k = 0; k < 64; k++) {
            float a[4], bb[4];
            #pragma unroll
            for (int i = 0; i < 4; i++) a[i] = KPs[(ty * 4 + i) * ATT_STRIDE + k];
            #pragma unroll
            for (int j = 0; j < 4; j++) bb[j] = Vs[k * ATT_STRIDE + tx * 4 + j];
            #pragma unroll
            for (int i = 0; i < 4; i++)
                #pragma unroll
                for (int j = 0; j < 4; j++)
                    acc[i][j] = fmaf(a[i], bb[j], acc[i][j]);
        }
        __syncthreads();  // before next K/V load overwrites tiles
    }

    // Normalize and write out: ao[b*T + tok][h*64 + d]
    #pragma unroll
    for (int i = 0; i < 4; i++) {
        float inv = 1.0f / l_i[i];
        size_t row = tokRowBase + qBase + ty * 4 + i;
        #pragma unroll
        for (int j = 0; j < 4; j++)
            ao[row * DIM + h * DH + tx * 4 + j] = acc[i][j] * inv;
    }
}

// ---------------------------------------------------------------------------
extern "C" void kernel_launch(void* const* d_in, const int* in_sizes, int n_in,
                              void* d_out, int out_size)
{
    const float* x      = (const float*)d_in[0];
    const float* gamma  = (const float*)d_in[1];
    const float* beta   = (const float*)d_in[2];
    const float* w_qkv  = (const float*)d_in[3];
    const float* w_out  = (const float*)d_in[4];
    const float* b_out  = (const float*)d_in[5];
    float* out = (float*)d_out;

    void* p;
    cudaGetSymbolAddress(&p, g_xn);  float* xn  = (float*)p;
    cudaGetSymbolAddress(&p, g_qkv); float* qkv = (float*)p;
    cudaGetSymbolAddress(&p, g_ao);  float* ao  = (float*)p;

    // 1) LayerNorm
    ln_kernel<<<NTOK, 256>>>(x, gamma, beta);

    // 2) QKV projection: [8192,1024] @ [1024,3072]
    sgemm_kernel<false><<<dim3(TRIPLE / 128, NTOK / 128), 256>>>(
        xn, w_qkv, qkv, NTOK, TRIPLE, DIM, nullptr);

    // 3) Attention
    int smem_bytes = ATT_SMEM_FLOATS * (int)sizeof(float); // 49,920 B
    cudaFuncSetAttribute(attn_kernel,
                         cudaFuncAttributeMaxDynamicSharedMemorySize, smem_bytes);
    attn_kernel<<<dim3(TSEQ / 64, NH, NB), 256, smem_bytes>>>(qkv, ao);

    // 4) Output projection + bias: [8192,1024] @ [1024,1024] + b
    sgemm_kernel<true><<<dim3(DIM / 128, NTOK / 128), 256>>>(
        ao, w_out, out, NTOK, DIM, DIM, b_out);
}

// round 4
// speedup vs baseline: 3.9519x; 3.9519x over previous
#include <cuda_runtime.h>
#include <math.h>
#include <stdint.h>

#define NTOK 8192
#define DIM 1024
#define TRIPLE 3072
#define TSEQ 2048
#define NB 4
#define NH 16
#define DH 64
#define ATT_SCALE 0.125f

// Scratch (allocation-free: device globals)
__device__ float g_xn[(size_t)NTOK * DIM];     // 32 MB
__device__ float g_qkv[(size_t)NTOK * TRIPLE]; // 96 MB
__device__ float g_ao[(size_t)NTOK * DIM];     // 32 MB

// ---------------------------------------------------------------------------
// Helpers: tf32 convert (round-to-nearest) + m16n8k8 tf32 mma
// ---------------------------------------------------------------------------
__device__ __forceinline__ float f2tf32(float f) {
    uint32_t r;
    asm("cvt.rna.tf32.f32 %0, %1;" : "=r"(r) : "f"(f));
    return __uint_as_float(r);
}

__device__ __forceinline__ float4 cvt4(float4 v) {
    float4 o;
    o.x = f2tf32(v.x); o.y = f2tf32(v.y); o.z = f2tf32(v.z); o.w = f2tf32(v.w);
    return o;
}

__device__ __forceinline__ void mma_tf32(float c[4],
                                         uint32_t a0, uint32_t a1, uint32_t a2, uint32_t a3,
                                         uint32_t b0, uint32_t b1) {
    asm volatile(
        "mma.sync.aligned.m16n8k8.row.col.f32.tf32.tf32.f32 "
        "{%0,%1,%2,%3}, {%4,%5,%6,%7}, {%8,%9}, {%0,%1,%2,%3};"
        : "+f"(c[0]), "+f"(c[1]), "+f"(c[2]), "+f"(c[3])
        : "r"(a0), "r"(a1), "r"(a2), "r"(a3), "r"(b0), "r"(b1));
}

// ---------------------------------------------------------------------------
// LayerNorm: one block per row of 1024, 256 threads x float4
// ---------------------------------------------------------------------------
__global__ __launch_bounds__(256) void ln_kernel(
    const float* __restrict__ x,
    const float* __restrict__ gamma,
    const float* __restrict__ beta)
{
    int row = blockIdx.x;
    int t = threadIdx.x;
    const float4* xr = reinterpret_cast<const float4*>(x) + (size_t)row * (DIM / 4);
    float4 v = xr[t];

    __shared__ float red[8];

    float s = v.x + v.y + v.z + v.w;
    #pragma unroll
    for (int o = 16; o > 0; o >>= 1) s += __shfl_xor_sync(0xffffffffu, s, o);
    if ((t & 31) == 0) red[t >> 5] = s;
    __syncthreads();
    float mu = 0.f;
    #pragma unroll
    for (int i = 0; i < 8; i++) mu += red[i];
    mu *= (1.0f / DIM);
    __syncthreads();

    float dx = v.x - mu, dy = v.y - mu, dz = v.z - mu, dw = v.w - mu;
    float s2 = dx * dx + dy * dy + dz * dz + dw * dw;
    #pragma unroll
    for (int o = 16; o > 0; o >>= 1) s2 += __shfl_xor_sync(0xffffffffu, s2, o);
    if ((t & 31) == 0) red[t >> 5] = s2;
    __syncthreads();
    float var = 0.f;
    #pragma unroll
    for (int i = 0; i < 8; i++) var += red[i];
    var *= (1.0f / DIM);
    float r = rsqrtf(var + 1e-5f);

    float4 g = reinterpret_cast<const float4*>(gamma)[t];
    float4 bb = reinterpret_cast<const float4*>(beta)[t];
    float4 o;
    o.x = dx * r * g.x + bb.x;
    o.y = dy * r * g.y + bb.y;
    o.z = dz * r * g.z + bb.z;
    o.w = dw * r * g.w + bb.w;
    reinterpret_cast<float4*>(g_xn)[(size_t)row * (DIM / 4) + t] = o;
}

// ---------------------------------------------------------------------------
// tf32 GEMM: C[M,N] = A[M,K] @ B[K,N] (+bias). 128x128x32 tiles, 256 threads.
// 8 warps as 4(m) x 2(n); warp tile 32x64 -> Mf=2 x Nf=8 m16n8k8 fragments.
// As[m][k] stride 36, Bs[k][n] stride 136: all fragment reads bank-conflict-free.
// ---------------------------------------------------------------------------
template <bool HAS_BIAS>
__global__ __launch_bounds__(256, 2) void gemm_tf32_kernel(
    const float* __restrict__ A,
    const float* __restrict__ Bm,
    float* __restrict__ C,
    int M, int N, int K,
    const float* __restrict__ bias)
{
    const int BK = 32;
    __shared__ __align__(16) float As[128][36];
    __shared__ __align__(16) float Bs[BK][136];

    int t = threadIdx.x;
    int lane = t & 31;
    int warp = t >> 5;
    int warp_m = warp & 3;   // 0..3 -> m offset *32
    int warp_n = warp >> 2;  // 0..1 -> n offset *64
    int grp = lane >> 2;     // 0..7
    int tg = lane & 3;       // 0..3
    int mBase = blockIdx.y * 128;
    int nBase = blockIdx.x * 128;

    float acc[2][8][4];
    #pragma unroll
    for (int mi = 0; mi < 2; mi++)
        #pragma unroll
        for (int f = 0; f < 8; f++)
            #pragma unroll
            for (int j = 0; j < 4; j++) acc[mi][f][j] = 0.f;

    for (int k0 = 0; k0 < K; k0 += BK) {
        // A tile: 128x32 = 1024 float4 / 256 threads
        #pragma unroll
        for (int i = 0; i < 4; i++) {
            int fid = t + i * 256;
            int ar = fid >> 3;
            int ak = (fid & 7) << 2;
            float4 v = *reinterpret_cast<const float4*>(
                &A[(size_t)(mBase + ar) * K + k0 + ak]);
            *reinterpret_cast<float4*>(&As[ar][ak]) = cvt4(v);
        }
        // B tile: 32x128 = 1024 float4
        #pragma unroll
        for (int i = 0; i < 4; i++) {
            int fid = t + i * 256;
            int br = fid >> 5;
            int bc = (fid & 31) << 2;
            float4 v = *reinterpret_cast<const float4*>(
                &Bm[(size_t)(k0 + br) * N + nBase + bc]);
            *reinterpret_cast<float4*>(&Bs[br][bc]) = cvt4(v);
        }
        __syncthreads();

        #pragma unroll
        for (int ks = 0; ks < 4; ks++) {
            int k = ks * 8;
            // B fragments: b0=(k=tg, n), b1=(k=tg+4, n)
            uint32_t bf[8][2];
            #pragma unroll
            for (int f = 0; f < 8; f++) {
                int n = warp_n * 64 + f * 8 + grp;
                bf[f][0] = __float_as_uint(Bs[k + tg][n]);
                bf[f][1] = __float_as_uint(Bs[k + tg + 4][n]);
            }
            // A fragments
            uint32_t af[2][4];
            #pragma unroll
            for (int mi = 0; mi < 2; mi++) {
                int m = warp_m * 32 + mi * 16;
                af[mi][0] = __float_as_uint(As[m + grp][k + tg]);
                af[mi][1] = __float_as_uint(As[m + grp + 8][k + tg]);
                af[mi][2] = __float_as_uint(As[m + grp][k + tg + 4]);
                af[mi][3] = __float_as_uint(As[m + grp + 8][k + tg + 4]);
            }
            #pragma unroll
            for (int mi = 0; mi < 2; mi++)
                #pragma unroll
                for (int f = 0; f < 8; f++)
                    mma_tf32(acc[mi][f], af[mi][0], af[mi][1], af[mi][2], af[mi][3],
                             bf[f][0], bf[f][1]);
        }
        __syncthreads();
    }

    // Epilogue: c0,c1 -> (row grp, cols 2tg..2tg+1); c2,c3 -> row grp+8
    #pragma unroll
    for (int mi = 0; mi < 2; mi++) {
        int r0 = mBase + warp_m * 32 + mi * 16 + grp;
        #pragma unroll
        for (int f = 0; f < 8; f++) {
            int col = nBase + warp_n * 64 + f * 8 + 2 * tg;
            float2 c01 = make_float2(acc[mi][f][0], acc[mi][f][1]);
            float2 c23 = make_float2(acc[mi][f][2], acc[mi][f][3]);
            if (HAS_BIAS) {
                float b0v = bias[col], b1v = bias[col + 1];
                c01.x += b0v; c01.y += b1v;
                c23.x += b0v; c23.y += b1v;
            }
            *reinterpret_cast<float2*>(&C[(size_t)r0 * N + col]) = c01;
            *reinterpret_cast<float2*>(&C[(size_t)(r0 + 8) * N + col]) = c23;
        }
    }
}

// ---------------------------------------------------------------------------
// Flash attention with tf32 tensor cores, fp32 online softmax.
// Block = (128-query tile, head, batch); 8 warps, warp owns 16 q rows.
// Q persistent in registers as A-fragments; QP smem buffer reused for P.
// smem floats: Ks[64][68], Vs[64][72], QPs[128][68]
// ---------------------------------------------------------------------------
#define KS_STRIDE 68
#define VS_STRIDE 72
#define QP_STRIDE 68
#define ATT_SMEM_FLOATS (64 * KS_STRIDE + 64 * VS_STRIDE + 128 * QP_STRIDE)

__global__ __launch_bounds__(256, 2) void attn_tc_kernel(
    const float* __restrict__ qkv,
    float* __restrict__ ao)
{
    extern __shared__ __align__(16) float sm[];
    float* Ks  = sm;                                  // [64][68]
    float* Vs  = sm + 64 * KS_STRIDE;                 // [64][72]
    float* QPs = sm + 64 * KS_STRIDE + 64 * VS_STRIDE;// [128][68]

    int t = threadIdx.x;
    int lane = t & 31;
    int warp = t >> 5;     // 0..7
    int grp = lane >> 2;   // 0..7
    int tg = lane & 3;     // 0..3
    int wq = warp * 16;    // this warp's q-row offset within tile

    int qtile = blockIdx.x;
    int h = blockIdx.y;
    int b = blockIdx.z;

    size_t tokRowBase = (size_t)b * TSEQ;
    const float* Qg = qkv + tokRowBase * TRIPLE + h * DH;
    const float* Kg = qkv + tokRowBase * TRIPLE + DIM + h * DH;
    const float* Vg = qkv + tokRowBase * TRIPLE + 2 * DIM + h * DH;
    int qBase = qtile * 128;

    // Stage this warp's 16 Q rows (scaled + tf32) into QPs, then load A-frags.
    #pragma unroll
    for (int i = 0; i < 8; i++) {
        int fid = i * 32 + lane;            // 0..255
        int r = fid >> 4;                   // 0..15
        int c = (fid & 15) << 2;            // 0..60
        float4 v = *reinterpret_cast<const float4*>(
            &Qg[(size_t)(qBase + wq + r) * TRIPLE + c]);
        v.x *= ATT_SCALE; v.y *= ATT_SCALE; v.z *= ATT_SCALE; v.w *= ATT_SCALE;
        *reinterpret_cast<float4*>(&QPs[(wq + r) * QP_STRIDE + c]) = cvt4(v);
    }
    __syncwarp();

    uint32_t qa[8][4];  // persistent Q fragments: 8 k-steps over d=64
    #pragma unroll
    for (int ks = 0; ks < 8; ks++) {
        int k = ks * 8;
        qa[ks][0] = __float_as_uint(QPs[(wq + grp) * QP_STRIDE + k + tg]);
        qa[ks][1] = __float_as_uint(QPs[(wq + grp + 8) * QP_STRIDE + k + tg]);
        qa[ks][2] = __float_as_uint(QPs[(wq + grp) * QP_STRIDE + k + tg + 4]);
        qa[ks][3] = __float_as_uint(QPs[(wq + grp + 8) * QP_STRIDE + k + tg + 4]);
    }

    float o_acc[8][4];
    #pragma unroll
    for (int f = 0; f < 8; f++)
        #pragma unroll
        for (int j = 0; j < 4; j++) o_acc[f][j] = 0.f;
    float m0 = -INFINITY, m1 = -INFINITY, l0 = 0.f, l1 = 0.f;

    for (int kt = 0; kt < TSEQ / 64; kt++) {
        __syncthreads();   // prior S/PV reads of Ks/Vs done before overwrite
        int kBase = kt * 64;
        // Load K and V tiles: 64x64 each, 1024 float4 total per tensor
        #pragma unroll
        for (int i = 0; i < 4; i++) {
            int fid = t + i * 256;
            int r = fid >> 4;
            int c = (fid & 15) << 2;
            float4 kv = *reinterpret_cast<const float4*>(
                &Kg[(size_t)(kBase + r) * TRIPLE + c]);
            *reinterpret_cast<float4*>(&Ks[r * KS_STRIDE + c]) = cvt4(kv);
            float4 vv = *reinterpret_cast<const float4*>(
                &Vg[(size_t)(kBase + r) * TRIPLE + c]);
            *reinterpret_cast<float4*>(&Vs[r * VS_STRIDE + c]) = cvt4(vv);
        }
        __syncthreads();

        // S = Q K^T : warp computes 16 x 64
        float s[8][4];
        #pragma unroll
        for (int f = 0; f < 8; f++)
            #pragma unroll
            for (int j = 0; j < 4; j++) s[f][j] = 0.f;
        #pragma unroll
        for (int ks = 0; ks < 8; ks++) {
            int k = ks * 8;   // d index
            #pragma unroll
            for (int f = 0; f < 8; f++) {
                int key = f * 8 + grp;
                uint32_t b0 = __float_as_uint(Ks[key * KS_STRIDE + k + tg]);
                uint32_t b1 = __float_as_uint(Ks[key * KS_STRIDE + k + tg + 4]);
                mma_tf32(s[f], qa[ks][0], qa[ks][1], qa[ks][2], qa[ks][3], b0, b1);
            }
        }

        // Online softmax for the thread's two rows
        float rm0 = -INFINITY, rm1 = -INFINITY;
        #pragma unroll
        for (int f = 0; f < 8; f++) {
            rm0 = fmaxf(rm0, fmaxf(s[f][0], s[f][1]));
            rm1 = fmaxf(rm1, fmaxf(s[f][2], s[f][3]));
        }
        #pragma unroll
        for (int o = 1; o <= 2; o <<= 1) {
            rm0 = fmaxf(rm0, __shfl_xor_sync(0xffffffffu, rm0, o));
            rm1 = fmaxf(rm1, __shfl_xor_sync(0xffffffffu, rm1, o));
        }
        float mn0 = fmaxf(m0, rm0), mn1 = fmaxf(m1, rm1);
        float a0 = __expf(m0 - mn0), a1 = __expf(m1 - mn1);
        float rs0 = 0.f, rs1 = 0.f;
        #pragma unroll
        for (int f = 0; f < 8; f++) {
            s[f][0] = __expf(s[f][0] - mn0);
            s[f][1] = __expf(s[f][1] - mn0);
            s[f][2] = __expf(s[f][2] - mn1);
            s[f][3] = __expf(s[f][3] - mn1);
            rs0 += s[f][0] + s[f][1];
            rs1 += s[f][2] + s[f][3];
        }
        #pragma unroll
        for (int o = 1; o <= 2; o <<= 1) {
            rs0 += __shfl_xor_sync(0xffffffffu, rs0, o);
            rs1 += __shfl_xor_sync(0xffffffffu, rs1, o);
        }
        l0 = l0 * a0 + rs0;
        l1 = l1 * a1 + rs1;
        m0 = mn0; m1 = mn1;
        #pragma unroll
        for (int f = 0; f < 8; f++) {
            o_acc[f][0] *= a0; o_acc[f][1] *= a0;
            o_acc[f][2] *= a1; o_acc[f][3] *= a1;
        }

        // Write P (tf32) into this warp's own QPs rows: [q][key]
        #pragma unroll
        for (int f = 0; f < 8; f++) {
            int col = f * 8 + 2 * tg;
            float2 p01 = make_float2(f2tf32(s[f][0]), f2tf32(s[f][1]));
            float2 p23 = make_float2(f2tf32(s[f][2]), f2tf32(s[f][3]));
            *reinterpret_cast<float2*>(&QPs[(wq + grp) * QP_STRIDE + col]) = p01;
            *reinterpret_cast<float2*>(&QPs[(wq + grp + 8) * QP_STRIDE + col]) = p23;
        }
        __syncwarp();

        // O += P @ V : k over 64 keys, n over 64 d
        #pragma unroll
        for (int ks = 0; ks < 8; ks++) {
            int k = ks * 8;   // key index
            uint32_t pa0 = __float_as_uint(QPs[(wq + grp) * QP_STRIDE + k + tg]);
            uint32_t pa1 = __float_as_uint(QPs[(wq + grp + 8) * QP_STRIDE + k + tg]);
            uint32_t pa2 = __float_as_uint(QPs[(wq + grp) * QP_STRIDE + k + tg + 4]);
            uint32_t pa3 = __float_as_uint(QPs[(wq + grp + 8) * QP_STRIDE + k + tg + 4]);
            #pragma unroll
            for (int f = 0; f < 8; f++) {
                int n = f * 8 + grp;   // d index
                uint32_t b0 = __float_as_uint(Vs[(k + tg) * VS_STRIDE + n]);
                uint32_t b1 = __float_as_uint(Vs[(k + tg + 4) * VS_STRIDE + n]);
                mma_tf32(o_acc[f], pa0, pa1, pa2, pa3, b0, b1);
            }
        }
    }

    // Normalize + write out
    float inv0 = 1.0f / l0, inv1 = 1.0f / l1;
    size_t gr0 = tokRowBase + qBase + wq + grp;
    size_t gr1 = gr0 + 8;
    #pragma unroll
    for (int f = 0; f < 8; f++) {
        int col = h * DH + f * 8 + 2 * tg;
        float2 c01 = make_float2(o_acc[f][0] * inv0, o_acc[f][1] * inv0);
        float2 c23 = make_float2(o_acc[f][2] * inv1, o_acc[f][3] * inv1);
        *reinterpret_cast<float2*>(&ao[gr0 * DIM + col]) = c01;
        *reinterpret_cast<float2*>(&ao[gr1 * DIM + col]) = c23;
    }
}

// ---------------------------------------------------------------------------
extern "C" void kernel_launch(void* const* d_in, const int* in_sizes, int n_in,
                              void* d_out, int out_size)
{
    const float* x      = (const float*)d_in[0];
    const float* gamma  = (const float*)d_in[1];
    const float* beta   = (const float*)d_in[2];
    const float* w_qkv  = (const float*)d_in[3];
    const float* w_out  = (const float*)d_in[4];
    const float* b_out  = (const float*)d_in[5];
    float* out = (float*)d_out;

    void* p;
    cudaGetSymbolAddress(&p, g_xn);  float* xn  = (float*)p;
    cudaGetSymbolAddress(&p, g_qkv); float* qkv = (float*)p;
    cudaGetSymbolAddress(&p, g_ao);  float* ao  = (float*)p;

    // 1) LayerNorm
    ln_kernel<<<NTOK, 256>>>(x, gamma, beta);

    // 2) QKV projection: [8192,1024] @ [1024,3072]
    gemm_tf32_kernel<false><<<dim3(TRIPLE / 128, NTOK / 128), 256>>>(
        xn, w_qkv, qkv, NTOK, TRIPLE, DIM, nullptr);

    // 3) Attention (tensor-core)
    int smem_bytes = ATT_SMEM_FLOATS * (int)sizeof(float); // 70,656 B
    cudaFuncSetAttribute(attn_tc_kernel,
                         cudaFuncAttributeMaxDynamicSharedMemorySize, smem_bytes);
    attn_tc_kernel<<<dim3(TSEQ / 128, NH, NB), 256, smem_bytes>>>(qkv, ao);

    // 4) Output projection + bias: [8192,1024] @ [1024,1024] + b
    gemm_tf32_kernel<true><<<dim3(DIM / 128, NTOK / 128), 256>>>(
        ao, w_out, out, NTOK, DIM, DIM, b_out);
}

// round 9
// speedup vs baseline: 4.5186x; 1.1434x over previous
#include <cuda_runtime.h>
#include <math.h>
#include <stdint.h>

#define NTOK 8192
#define DIM 1024
#define TRIPLE 3072
#define TSEQ 2048
#define NB 4
#define NH 16
#define DH 64
#define ATT_SCALE 0.125f

// Scratch (allocation-free: device globals)
__device__ float g_xn[(size_t)NTOK * DIM];       // 32 MB (tf32-rounded)
__device__ float g_qkv[(size_t)NTOK * TRIPLE];   // 96 MB (tf32-rounded)
__device__ float g_ao[(size_t)NTOK * DIM];       // 32 MB (tf32-rounded)
__device__ float g_wqkv[(size_t)DIM * TRIPLE];   // 12 MB (tf32-rounded weights)
__device__ float g_wout[(size_t)DIM * DIM];      //  4 MB

// ---------------------------------------------------------------------------
// Helpers
// ---------------------------------------------------------------------------
__device__ __forceinline__ float f2tf32(float f) {
    uint32_t r;
    asm("cvt.rna.tf32.f32 %0, %1;" : "=r"(r) : "f"(f));
    return __uint_as_float(r);
}

__device__ __forceinline__ float4 cvt4(float4 v) {
    float4 o;
    o.x = f2tf32(v.x); o.y = f2tf32(v.y); o.z = f2tf32(v.z); o.w = f2tf32(v.w);
    return o;
}

__device__ __forceinline__ void mma_tf32(float c[4],
                                         uint32_t a0, uint32_t a1, uint32_t a2, uint32_t a3,
                                         uint32_t b0, uint32_t b1) {
    asm volatile(
        "mma.sync.aligned.m16n8k8.row.col.f32.tf32.tf32.f32 "
        "{%0,%1,%2,%3}, {%4,%5,%6,%7}, {%8,%9}, {%0,%1,%2,%3};"
        : "+f"(c[0]), "+f"(c[1]), "+f"(c[2]), "+f"(c[3])
        : "r"(a0), "r"(a1), "r"(a2), "r"(a3), "r"(b0), "r"(b1));
}

__device__ __forceinline__ void cp16(void* smem_dst, const void* gmem_src) {
    uint32_t s = (uint32_t)__cvta_generic_to_shared(smem_dst);
    asm volatile("cp.async.cg.shared.global [%0], [%1], 16;" :: "r"(s), "l"(gmem_src));
}
#define CP_COMMIT() asm volatile("cp.async.commit_group;" ::: "memory")
#define CP_WAIT0()  asm volatile("cp.async.wait_group 0;" ::: "memory")

// ---------------------------------------------------------------------------
// Weight rounding: fp32 -> tf32-rounded fp32 (grid-stride float4)
// ---------------------------------------------------------------------------
__global__ __launch_bounds__(256) void round_w_kernel(
    const float* __restrict__ in, float* __restrict__ out, int n4)
{
    int i = blockIdx.x * blockDim.x + threadIdx.x;
    if (i < n4) {
        float4 v = reinterpret_cast<const float4*>(in)[i];
        reinterpret_cast<float4*>(out)[i] = cvt4(v);
    }
}

// ---------------------------------------------------------------------------
// LayerNorm: one block per row of 1024, 256 threads x float4. Output tf32-rounded.
// ---------------------------------------------------------------------------
__global__ __launch_bounds__(256) void ln_kernel(
    const float* __restrict__ x,
    const float* __restrict__ gamma,
    const float* __restrict__ beta)
{
    int row = blockIdx.x;
    int t = threadIdx.x;
    const float4* xr = reinterpret_cast<const float4*>(x) + (size_t)row * (DIM / 4);
    float4 v = xr[t];

    __shared__ float red[8];

    float s = v.x + v.y + v.z + v.w;
    #pragma unroll
    for (int o = 16; o > 0; o >>= 1) s += __shfl_xor_sync(0xffffffffu, s, o);
    if ((t & 31) == 0) red[t >> 5] = s;
    __syncthreads();
    float mu = 0.f;
    #pragma unroll
    for (int i = 0; i < 8; i++) mu += red[i];
    mu *= (1.0f / DIM);
    __syncthreads();

    float dx = v.x - mu, dy = v.y - mu, dz = v.z - mu, dw = v.w - mu;
    float s2 = dx * dx + dy * dy + dz * dz + dw * dw;
    #pragma unroll
    for (int o = 16; o > 0; o >>= 1) s2 += __shfl_xor_sync(0xffffffffu, s2, o);
    if ((t & 31) == 0) red[t >> 5] = s2;
    __syncthreads();
    float var = 0.f;
    #pragma unroll
    for (int i = 0; i < 8; i++) var += red[i];
    var *= (1.0f / DIM);
    float r = rsqrtf(var + 1e-5f);

    float4 g = reinterpret_cast<const float4*>(gamma)[t];
    float4 bb = reinterpret_cast<const float4*>(beta)[t];
    float4 o;
    o.x = dx * r * g.x + bb.x;
    o.y = dy * r * g.y + bb.y;
    o.z = dz * r * g.z + bb.z;
    o.w = dw * r * g.w + bb.w;
    reinterpret_cast<float4*>(g_xn)[(size_t)row * (DIM / 4) + t] = cvt4(o);
}

// ---------------------------------------------------------------------------
// tf32 GEMM, cp.async double-buffered. C[M,N] = A[M,K] @ B[K,N] (+bias).
// CTA tile 128x128x32, 128 threads = 4 warps (2m x 2n), warp tile 64x64.
// Inputs must be pre-rounded to tf32. LDS/mma = 1.0.
// Dyn smem: As[2][128][36], Bs[2][32][136] = 71,680 B.
// ---------------------------------------------------------------------------
#define GS_AS (128 * 36)
#define GS_BS (32 * 136)
#define GEMM_SMEM_BYTES ((2 * GS_AS + 2 * GS_BS) * (int)sizeof(float))

template <bool HAS_BIAS, bool ROUND_OUT>
__global__ __launch_bounds__(128, 2) void gemm_tf32_pipe(
    const float* __restrict__ A,
    const float* __restrict__ Bm,
    float* __restrict__ C,
    int M, int N, int K,
    const float* __restrict__ bias)
{
    extern __shared__ __align__(16) float smg[];
    float* AsBase = smg;                 // [2][128][36]
    float* BsBase = smg + 2 * GS_AS;     // [2][32][136]

    int t = threadIdx.x;
    int lane = t & 31;
    int warp = t >> 5;       // 0..3
    int warp_m = warp & 1;   // m offset *64
    int warp_n = warp >> 1;  // n offset *64
    int grp = lane >> 2;     // 0..7
    int tg = lane & 3;       // 0..3
    int mBase = blockIdx.y * 128;
    int nBase = blockIdx.x * 128;

    float acc[4][8][4];
    #pragma unroll
    for (int mi = 0; mi < 4; mi++)
        #pragma unroll
        for (int f = 0; f < 8; f++)
            #pragma unroll
            for (int j = 0; j < 4; j++) acc[mi][f][j] = 0.f;

    // Prefetch tile 0
    {
        float* As = AsBase;
        float* Bs = BsBase;
        #pragma unroll
        for (int i = 0; i < 8; i++) {
            int fid = t + i * 128;
            int ar = fid >> 3, ak = (fid & 7) << 2;
            cp16(&As[ar * 36 + ak], &A[(size_t)(mBase + ar) * K + ak]);
        }
        #pragma unroll
        for (int i = 0; i < 8; i++) {
            int fid = t + i * 128;
            int br = fid >> 5, bc = (fid & 31) << 2;
            cp16(&Bs[br * 136 + bc], &Bm[(size_t)br * N + nBase + bc]);
        }
        CP_COMMIT();
    }

    int T = K / 32;
    for (int kt = 0; kt < T; kt++) {
        CP_WAIT0();
        __syncthreads();
        if (kt + 1 < T) {
            int k0 = (kt + 1) * 32;
            int sn = (kt + 1) & 1;
            float* As = AsBase + sn * GS_AS;
            float* Bs = BsBase + sn * GS_BS;
            #pragma unroll
            for (int i = 0; i < 8; i++) {
                int fid = t + i * 128;
                int ar = fid >> 3, ak = (fid & 7) << 2;
                cp16(&As[ar * 36 + ak], &A[(size_t)(mBase + ar) * K + k0 + ak]);
            }
            #pragma unroll
            for (int i = 0; i < 8; i++) {
                int fid = t + i * 128;
                int br = fid >> 5, bc = (fid & 31) << 2;
                cp16(&Bs[br * 136 + bc], &Bm[(size_t)(k0 + br) * N + nBase + bc]);
            }
            CP_COMMIT();
        }

        const float* As = AsBase + (kt & 1) * GS_AS;
        const float* Bs = BsBase + (kt & 1) * GS_BS;
        #pragma unroll
        for (int ks = 0; ks < 4; ks++) {
            int k = ks * 8;
            uint32_t af[4][4];
            #pragma unroll
            for (int mi = 0; mi < 4; mi++) {
                int m = warp_m * 64 + mi * 16;
                af[mi][0] = __float_as_uint(As[(m + grp) * 36 + k + tg]);
                af[mi][1] = __float_as_uint(As[(m + grp + 8) * 36 + k + tg]);
                af[mi][2] = __float_as_uint(As[(m + grp) * 36 + k + tg + 4]);
                af[mi][3] = __float_as_uint(As[(m + grp + 8) * 36 + k + tg + 4]);
            }
            uint32_t bf[8][2];
            #pragma unroll
            for (int f = 0; f < 8; f++) {
                int n = warp_n * 64 + f * 8 + grp;
                bf[f][0] = __float_as_uint(Bs[(k + tg) * 136 + n]);
                bf[f][1] = __float_as_uint(Bs[(k + tg + 4) * 136 + n]);
            }
            #pragma unroll
            for (int mi = 0; mi < 4; mi++)
                #pragma unroll
                for (int f = 0; f < 8; f++)
                    mma_tf32(acc[mi][f], af[mi][0], af[mi][1], af[mi][2], af[mi][3],
                             bf[f][0], bf[f][1]);
        }
        // No trailing barrier: stage (kt&1) is next written by copy kt+2, which
        // every thread issues only after passing the kt+1 top barrier.
    }

    // Epilogue
    #pragma unroll
    for (int mi = 0; mi < 4; mi++) {
        int r0 = mBase + warp_m * 64 + mi * 16 + grp;
        #pragma unroll
        for (int f = 0; f < 8; f++) {
            int col = nBase + warp_n * 64 + f * 8 + 2 * tg;
            float2 c01 = make_float2(acc[mi][f][0], acc[mi][f][1]);
            float2 c23 = make_float2(acc[mi][f][2], acc[mi][f][3]);
            if (HAS_BIAS) {
                float b0v = bias[col], b1v = bias[col + 1];
                c01.x += b0v; c01.y += b1v;
                c23.x += b0v; c23.y += b1v;
            }
            if (ROUND_OUT) {
                c01.x = f2tf32(c01.x); c01.y = f2tf32(c01.y);
                c23.x = f2tf32(c23.x); c23.y = f2tf32(c23.y);
            }
            *reinterpret_cast<float2*>(&C[(size_t)r0 * N + col]) = c01;
            *reinterpret_cast<float2*>(&C[(size_t)(r0 + 8) * N + col]) = c23;
        }
    }
}

// ---------------------------------------------------------------------------
// Flash attention with tf32 tensor cores, fp32 online softmax, cp.async K/V
// double buffering. Block = (128-query tile, head, batch); 8 warps x 16 q rows.
// qkv is pre-rounded tf32; Q scale 0.125 is exact so no re-rounding needed.
// Dyn smem floats: Ks[2][64][68], Vs[2][64][72], QPs[128][68] = 106,496 B.
// ---------------------------------------------------------------------------
#define KS_STRIDE 68
#define VS_STRIDE 72
#define QP_STRIDE 68
#define AT_KS (64 * KS_STRIDE)
#define AT_VS (64 * VS_STRIDE)
#define ATT_SMEM_FLOATS (2 * AT_KS + 2 * AT_VS + 128 * QP_STRIDE)

__global__ __launch_bounds__(256, 2) void attn_tc_kernel(
    const float* __restrict__ qkv,
    float* __restrict__ ao)
{
    extern __shared__ __align__(16) float sm[];
    float* KsBase = sm;                       // [2][64][68]
    float* VsBase = sm + 2 * AT_KS;           // [2][64][72]
    float* QPs    = sm + 2 * AT_KS + 2 * AT_VS; // [128][68]

    int t = threadIdx.x;
    int lane = t & 31;
    int warp = t >> 5;     // 0..7
    int grp = lane >> 2;   // 0..7
    int tg = lane & 3;     // 0..3
    int wq = warp * 16;

    int qtile = blockIdx.x;
    int h = blockIdx.y;
    int b = blockIdx.z;

    size_t tokRowBase = (size_t)b * TSEQ;
    const float* Qg = qkv + tokRowBase * TRIPLE + h * DH;
    const float* Kg = qkv + tokRowBase * TRIPLE + DIM + h * DH;
    const float* Vg = qkv + tokRowBase * TRIPLE + 2 * DIM + h * DH;
    int qBase = qtile * 128;

    // Prefetch K/V tile 0 into stage 0
    {
        float* Ks = KsBase;
        float* Vs = VsBase;
        #pragma unroll
        for (int i = 0; i < 4; i++) {
            int fid = t + i * 256;
            int r = fid >> 4, c = (fid & 15) << 2;
            cp16(&Ks[r * KS_STRIDE + c], &Kg[(size_t)r * TRIPLE + c]);
            cp16(&Vs[r * VS_STRIDE + c], &Vg[(size_t)r * TRIPLE + c]);
        }
        CP_COMMIT();
    }

    // Stage this warp's 16 Q rows (scaled; qkv pre-rounded, x0.125 exact)
    #pragma unroll
    for (int i = 0; i < 8; i++) {
        int fid = i * 32 + lane;
        int r = fid >> 4;
        int c = (fid & 15) << 2;
        float4 v = *reinterpret_cast<const float4*>(
            &Qg[(size_t)(qBase + wq + r) * TRIPLE + c]);
        v.x *= ATT_SCALE; v.y *= ATT_SCALE; v.z *= ATT_SCALE; v.w *= ATT_SCALE;
        *reinterpret_cast<float4*>(&QPs[(wq + r) * QP_STRIDE + c]) = v;
    }
    __syncwarp();

    uint32_t qa[8][4];
    #pragma unroll
    for (int ks = 0; ks < 8; ks++) {
        int k = ks * 8;
        qa[ks][0] = __float_as_uint(QPs[(wq + grp) * QP_STRIDE + k + tg]);
        qa[ks][1] = __float_as_uint(QPs[(wq + grp + 8) * QP_STRIDE + k + tg]);
        qa[ks][2] = __float_as_uint(QPs[(wq + grp) * QP_STRIDE + k + tg + 4]);
        qa[ks][3] = __float_as_uint(QPs[(wq + grp + 8) * QP_STRIDE + k + tg + 4]);
    }

    float o_acc[8][4];
    #pragma unroll
    for (int f = 0; f < 8; f++)
        #pragma unroll
        for (int j = 0; j < 4; j++) o_acc[f][j] = 0.f;
    float m0 = -INFINITY, m1 = -INFINITY, l0 = 0.f, l1 = 0.f;

    const int NT = TSEQ / 64;
    for (int kt = 0; kt < NT; kt++) {
        CP_WAIT0();
        __syncthreads();
        if (kt + 1 < NT) {
            int kBase = (kt + 1) * 64;
            int sn = (kt + 1) & 1;
            float* Ks = KsBase + sn * AT_KS;
            float* Vs = VsBase + sn * AT_VS;
            #pragma unroll
            for (int i = 0; i < 4; i++) {
                int fid = t + i * 256;
                int r = fid >> 4, c = (fid & 15) << 2;
                cp16(&Ks[r * KS_STRIDE + c], &Kg[(size_t)(kBase + r) * TRIPLE + c]);
                cp16(&Vs[r * VS_STRIDE + c], &Vg[(size_t)(kBase + r) * TRIPLE + c]);
            }
            CP_COMMIT();
        }
        const float* Ks = KsBase + (kt & 1) * AT_KS;
        const float* Vs = VsBase + (kt & 1) * AT_VS;

        // S = Q K^T : warp computes 16 x 64
        float s[8][4];
        #pragma unroll
        for (int f = 0; f < 8; f++)
            #pragma unroll
            for (int j = 0; j < 4; j++) s[f][j] = 0.f;
        #pragma unroll
        for (int ks = 0; ks < 8; ks++) {
            int k = ks * 8;
            #pragma unroll
            for (int f = 0; f < 8; f++) {
                int key = f * 8 + grp;
                uint32_t b0 = __float_as_uint(Ks[key * KS_STRIDE + k + tg]);
                uint32_t b1 = __float_as_uint(Ks[key * KS_STRIDE + k + tg + 4]);
                mma_tf32(s[f], qa[ks][0], qa[ks][1], qa[ks][2], qa[ks][3], b0, b1);
            }
        }

        // Online softmax for the thread's two rows
        float rm0 = -INFINITY, rm1 = -INFINITY;
        #pragma unroll
        for (int f = 0; f < 8; f++) {
            rm0 = fmaxf(rm0, fmaxf(s[f][0], s[f][1]));
            rm1 = fmaxf(rm1, fmaxf(s[f][2], s[f][3]));
        }
        #pragma unroll
        for (int o = 1; o <= 2; o <<= 1) {
            rm0 = fmaxf(rm0, __shfl_xor_sync(0xffffffffu, rm0, o));
            rm1 = fmaxf(rm1, __shfl_xor_sync(0xffffffffu, rm1, o));
        }
        float mn0 = fmaxf(m0, rm0), mn1 = fmaxf(m1, rm1);
        float a0 = __expf(m0 - mn0), a1 = __expf(m1 - mn1);
        float rs0 = 0.f, rs1 = 0.f;
        #pragma unroll
        for (int f = 0; f < 8; f++) {
            s[f][0] = __expf(s[f][0] - mn0);
            s[f][1] = __expf(s[f][1] - mn0);
            s[f][2] = __expf(s[f][2] - mn1);
            s[f][3] = __expf(s[f][3] - mn1);
            rs0 += s[f][0] + s[f][1];
            rs1 += s[f][2] + s[f][3];
        }
        #pragma unroll
        for (int o = 1; o <= 2; o <<= 1) {
            rs0 += __shfl_xor_sync(0xffffffffu, rs0, o);
            rs1 += __shfl_xor_sync(0xffffffffu, rs1, o);
        }
        l0 = l0 * a0 + rs0;
        l1 = l1 * a1 + rs1;
        m0 = mn0; m1 = mn1;
        #pragma unroll
        for (int f = 0; f < 8; f++) {
            o_acc[f][0] *= a0; o_acc[f][1] *= a0;
            o_acc[f][2] *= a1; o_acc[f][3] *= a1;
        }

        // Write P (tf32) into this warp's own QPs rows: [q][key]
        #pragma unroll
        for (int f = 0; f < 8; f++) {
            int col = f * 8 + 2 * tg;
            float2 p01 = make_float2(f2tf32(s[f][0]), f2tf32(s[f][1]));
            float2 p23 = make_float2(f2tf32(s[f][2]), f2tf32(s[f][3]));
            *reinterpret_cast<float2*>(&QPs[(wq + grp) * QP_STRIDE + col]) = p01;
            *reinterpret_cast<float2*>(&QPs[(wq + grp + 8) * QP_STRIDE + col]) = p23;
        }
        __syncwarp();

        // O += P @ V
        #pragma unroll
        for (int ks = 0; ks < 8; ks++) {
            int k = ks * 8;
            uint32_t pa0 = __float_as_uint(QPs[(wq + grp) * QP_STRIDE + k + tg]);
            uint32_t pa1 = __float_as_uint(QPs[(wq + grp + 8) * QP_STRIDE + k + tg]);
            uint32_t pa2 = __float_as_uint(QPs[(wq + grp) * QP_STRIDE + k + tg + 4]);
            uint32_t pa3 = __float_as_uint(QPs[(wq + grp + 8) * QP_STRIDE + k + tg + 4]);
            #pragma unroll
            for (int f = 0; f < 8; f++) {
                int n = f * 8 + grp;
                uint32_t b0 = __float_as_uint(Vs[(k + tg) * VS_STRIDE + n]);
                uint32_t b1 = __float_as_uint(Vs[(k + tg + 4) * VS_STRIDE + n]);
                mma_tf32(o_acc[f], pa0, pa1, pa2, pa3, b0, b1);
            }
        }
        // No trailing barrier: stage (kt&1) next written by copy kt+2 issued
        // after the kt+1 top barrier.
    }

    // Normalize + write out (tf32-rounded for the out-projection consumer)
    float inv0 = 1.0f / l0, inv1 = 1.0f / l1;
    size_t gr0 = tokRowBase + qBase + wq + grp;
    size_t gr1 = gr0 + 8;
    #pragma unroll
    for (int f = 0; f < 8; f++) {
        int col = h * DH + f * 8 + 2 * tg;
        float2 c01 = make_float2(f2tf32(o_acc[f][0] * inv0), f2tf32(o_acc[f][1] * inv0));
        float2 c23 = make_float2(f2tf32(o_acc[f][2] * inv1), f2tf32(o_acc[f][3] * inv1));
        *reinterpret_cast<float2*>(&ao[gr0 * DIM + col]) = c01;
        *reinterpret_cast<float2*>(&ao[gr1 * DIM + col]) = c23;
    }
}

// ---------------------------------------------------------------------------
extern "C" void kernel_launch(void* const* d_in, const int* in_sizes, int n_in,
                              void* d_out, int out_size)
{
    const float* x      = (const float*)d_in[0];
    const float* gamma  = (const float*)d_in[1];
    const float* beta   = (const float*)d_in[2];
    const float* w_qkv  = (const float*)d_in[3];
    const float* w_out  = (const float*)d_in[4];
    const float* b_out  = (const float*)d_in[5];
    float* out = (float*)d_out;

    void* p;
    cudaGetSymbolAddress(&p, g_xn);   float* xn    = (float*)p;
    cudaGetSymbolAddress(&p, g_qkv);  float* qkv   = (float*)p;
    cudaGetSymbolAddress(&p, g_ao);   float* ao    = (float*)p;
    cudaGetSymbolAddress(&p, g_wqkv); float* wqkvt = (float*)p;
    cudaGetSymbolAddress(&p, g_wout); float* woutt = (float*)p;

    // 0) Round weights to tf32 once per launch (cheap, memory-bound)
    round_w_kernel<<<(DIM * TRIPLE / 4 + 255) / 256, 256>>>(w_qkv, wqkvt, DIM * TRIPLE / 4);
    round_w_kernel<<<(DIM * DIM / 4 + 255) / 256, 256>>>(w_out, woutt, DIM * DIM / 4);

    // 1) LayerNorm (writes tf32-rounded xn)
    ln_kernel<<<NTOK, 256>>>(x, gamma, beta);

    // 2) QKV projection: [8192,1024] @ [1024,3072] -> tf32-rounded qkv
    cudaFuncSetAttribute(gemm_tf32_pipe<false, true>,
                         cudaFuncAttributeMaxDynamicSharedMemorySize, GEMM_SMEM_BYTES);
    gemm_tf32_pipe<false, true><<<dim3(TRIPLE / 128, NTOK / 128), 128, GEMM_SMEM_BYTES>>>(
        xn, wqkvt, qkv, NTOK, TRIPLE, DIM, nullptr);

    // 3) Attention (tensor-core, cp.async pipelined)
    int att_smem = ATT_SMEM_FLOATS * (int)sizeof(float); // 106,496 B
    cudaFuncSetAttribute(attn_tc_kernel,
                         cudaFuncAttributeMaxDynamicSharedMemorySize, att_smem);
    attn_tc_kernel<<<dim3(TSEQ / 128, NH, NB), 256, att_smem>>>(qkv, ao);

    // 4) Output projection + bias: [8192,1024] @ [1024,1024] + b
    cudaFuncSetAttribute(gemm_tf32_pipe<true, false>,
                         cudaFuncAttributeMaxDynamicSharedMemorySize, GEMM_SMEM_BYTES);
    gemm_tf32_pipe<true, false><<<dim3(DIM / 128, NTOK / 128), 128, GEMM_SMEM_BYTES>>>(
        ao, woutt, out, NTOK, DIM, DIM, b_out);
}